// round 12
// baseline (speedup 1.0000x reference)
#include <cuda_runtime.h>
#include <cuda_fp16.h>
#include <cstdint>
#include <cstddef>

#define N_NODES  50000
#define N_EDGES  800000
#define N_GRAPHS 128
#define IN_C     128
#define HID_C    256
#define OUT_C    128
#define NB_SCAN  ((N_NODES + 255) / 256)   // 196

// ---------------- scratch (static device globals; no allocs) ----------------
__device__ int    g_indeg[N_NODES];
__device__ int    g_cursor[N_NODES];
__device__ int    g_offsets[N_NODES + 1];
__device__ int    g_bsum[256];
__device__ int    g_gbar[4];
__device__ int    g_csr_src[N_EDGES];
__device__ float  g_dinv[N_NODES];
__device__ __half g_xh  [(size_t)N_NODES * IN_C];
__device__ __half g_w1t [IN_C * HID_C];     // [N][K] = [256][128]
__device__ __half g_w2t [HID_C * HID_C];    // [256][256]
__device__ __half g_aggx[(size_t)N_NODES * IN_C];
__device__ __half g_h1  [(size_t)N_NODES * HID_C];
__device__ __half g_aggh[(size_t)N_NODES * HID_C];
__device__ float  g_pool[N_GRAPHS * HID_C];
__device__ int    g_cnt [N_GRAPHS];

// ---- fused converts + zeroing: x->half, W1t, W2t, zero state + barriers ----
#define CVT_R0 (N_NODES * IN_C / 4)          // 1,600,000
#define CVT_R1 (IN_C * HID_C)                // 32768
#define CVT_R2 (HID_C * HID_C)               // 65536
__global__ void __launch_bounds__(256)
cvt_all_kernel(const float4* __restrict__ x,
               const float* __restrict__ W1, const float* __restrict__ W2) {
    int i = blockIdx.x * blockDim.x + threadIdx.x;
    if (i < N_NODES) { g_indeg[i] = 0; g_cursor[i] = 0; }
    if (i < N_GRAPHS) g_cnt[i] = 0;
    if (i < N_GRAPHS * HID_C) g_pool[i] = 0.0f;
    if (i < 4) g_gbar[i] = 0;

    if (i < CVT_R0) {
        float4 v = x[i];
        uint2 u;
        __half2 lo = __floats2half2_rn(v.x, v.y);
        __half2 hi = __floats2half2_rn(v.z, v.w);
        u.x = *(uint32_t*)&lo; u.y = *(uint32_t*)&hi;
        ((uint2*)g_xh)[i] = u;
        return;
    }
    int j = i - CVT_R0;
    if (j < CVT_R1) {   // W1 [K=128][N=256] -> W1t [N][K]
        int k = j / HID_C, n = j % HID_C;
        g_w1t[n * IN_C + k] = __float2half(W1[j]);
        return;
    }
    int m = j - CVT_R1;
    if (m < CVT_R2) {   // W2 [256][256] -> W2t
        int k = m / HID_C, n = m % HID_C;
        g_w2t[n * HID_C + k] = __float2half(W2[m]);
    }
}

// ---------------- single-kernel CSR build (hist + scan + bin) ----------------
__device__ __forceinline__ int warp_incl_scan(int v, int lane) {
    #pragma unroll
    for (int off = 1; off < 32; off <<= 1) {
        int t = __shfl_up_sync(0xffffffffu, v, off);
        if (lane >= off) v += t;
    }
    return v;
}

// software grid barrier: valid because 196 blocks of 256 thr are all resident
__device__ __forceinline__ void grid_sync(int id, int nb) {
    __syncthreads();
    if (threadIdx.x == 0) {
        __threadfence();
        atomicAdd(&g_gbar[id], 1);
        while (atomicAdd(&g_gbar[id], 0) < nb) { }
    }
    __syncthreads();
}

__global__ void __launch_bounds__(256)
csr_build_kernel(const int* __restrict__ src, const int* __restrict__ dst,
                 const int* __restrict__ batch) {
    const int NB = NB_SCAN;
    const int GS = NB * 256;
    int t = threadIdx.x, lane = t & 31, wid = t >> 5;
    int gtid = blockIdx.x * 256 + t;

    // phase 1: degree histogram + per-graph node counts
    for (int e = gtid; e < N_EDGES; e += GS) atomicAdd(&g_indeg[dst[e]], 1);
    for (int i = gtid; i < N_NODES; i += GS) atomicAdd(&g_cnt[batch[i]], 1);
    grid_sync(0, NB);

    // phase 2: per-chunk inclusive scan -> offsets[i+1]; block total; dinv
    __shared__ int wsum[8];
    {
        int i = gtid;
        int v = (i < N_NODES) ? g_indeg[i] : 0;
        if (i < N_NODES) g_dinv[i] = rsqrtf((float)(v + 1));  // +1 self loop
        int incl = warp_incl_scan(v, lane);
        if (lane == 31) wsum[wid] = incl;
        __syncthreads();
        if (wid == 0) {
            int s = (lane < 8) ? wsum[lane] : 0;
            s = warp_incl_scan(s, lane);
            if (lane < 8) wsum[lane] = s;
        }
        __syncthreads();
        int base = (wid > 0) ? wsum[wid - 1] : 0;
        incl += base;
        if (i < N_NODES) g_offsets[i + 1] = incl;
        if (t == 255) g_bsum[blockIdx.x] = incl;
    }
    grid_sync(1, NB);

    // phase 3: add exclusive base (redundant per-block reduce of 196 ints)
    {
        __shared__ int s_base;
        int v = (t < NB && t < blockIdx.x) ? g_bsum[t] : 0;
        #pragma unroll
        for (int off = 16; off > 0; off >>= 1)
            v += __shfl_down_sync(0xffffffffu, v, off);
        __shared__ int w2[8];
        if (lane == 0) w2[wid] = v;
        __syncthreads();
        if (t == 0) {
            int s = 0;
            #pragma unroll
            for (int j = 0; j < 8; j++) s += w2[j];
            s_base = s;
        }
        __syncthreads();
        if (gtid < N_NODES) g_offsets[gtid + 1] += s_base;
        if (gtid == 0) g_offsets[0] = 0;
    }
    grid_sync(2, NB);

    // phase 4: bin edges into CSR
    for (int e = gtid; e < N_EDGES; e += GS) {
        int d = dst[e];
        int p = atomicAdd(&g_cursor[d], 1);
        g_csr_src[g_offsets[d] + p] = src[e];
    }
}

// ---------------- aggregation: one warp per node, streaming fp16 gather ----------------
template <int F>
__device__ __forceinline__ void ld_row_cs(const __half* __restrict__ X, int node, int lane,
                                          __half2 (&v)[F / 64]) {
    constexpr int C = F / 64;
    const __half2* xs = (const __half2*)(X + (size_t)node * F) + lane * C;
    if constexpr (C == 2) {
        uint2 u = __ldcs((const uint2*)xs);
        v[0] = *(__half2*)&u.x; v[1] = *(__half2*)&u.y;
    } else {
        uint4 u = __ldcs((const uint4*)xs);
        v[0] = *(__half2*)&u.x; v[1] = *(__half2*)&u.y;
        v[2] = *(__half2*)&u.z; v[3] = *(__half2*)&u.w;
    }
}

template <int F>
__global__ void __launch_bounds__(256)
agg_h_kernel(const __half* __restrict__ X, __half* __restrict__ O) {
    int warp = (blockIdx.x * blockDim.x + threadIdx.x) >> 5;
    int lane = threadIdx.x & 31;
    if (warp >= N_NODES) return;
    constexpr int C = F / 64;   // half2 per lane (2 or 4)
    float di = g_dinv[warp];
    float wself = di * di;

    float2 acc[C];
    {
        __half2 v[C];
        ld_row_cs<F>(X, warp, lane, v);
        #pragma unroll
        for (int j = 0; j < C; j++) {
            float2 f = __half22float2(v[j]);
            acc[j].x = wself * f.x; acc[j].y = wself * f.y;
        }
    }
    int e0 = g_offsets[warp];
    int e1 = g_offsets[warp + 1];
    int e  = e0;
    // unrolled x4: four row-gathers in flight per warp
    for (; e + 3 < e1; e += 4) {
        int s0 = g_csr_src[e],     s1 = g_csr_src[e + 1];
        int s2 = g_csr_src[e + 2], s3 = g_csr_src[e + 3];
        float w0 = g_dinv[s0] * di, w1 = g_dinv[s1] * di;
        float w2 = g_dinv[s2] * di, w3 = g_dinv[s3] * di;
        __half2 v0[C], v1[C], v2[C], v3[C];
        ld_row_cs<F>(X, s0, lane, v0);
        ld_row_cs<F>(X, s1, lane, v1);
        ld_row_cs<F>(X, s2, lane, v2);
        ld_row_cs<F>(X, s3, lane, v3);
        #pragma unroll
        for (int j = 0; j < C; j++) {
            float2 f0 = __half22float2(v0[j]);
            float2 f1 = __half22float2(v1[j]);
            float2 f2 = __half22float2(v2[j]);
            float2 f3 = __half22float2(v3[j]);
            acc[j].x += w0 * f0.x + w1 * f1.x + w2 * f2.x + w3 * f3.x;
            acc[j].y += w0 * f0.y + w1 * f1.y + w2 * f2.y + w3 * f3.y;
        }
    }
    for (; e < e1; e++) {
        int s = g_csr_src[e];
        float w = g_dinv[s] * di;
        __half2 v[C];
        ld_row_cs<F>(X, s, lane, v);
        #pragma unroll
        for (int j = 0; j < C; j++) {
            float2 f = __half22float2(v[j]);
            acc[j].x += w * f.x; acc[j].y += w * f.y;
        }
    }
    __half2* o = (__half2*)(O + (size_t)warp * F) + lane * C;
    if constexpr (C == 2) {
        uint2 u;
        __half2 h0 = __floats2half2_rn(acc[0].x, acc[0].y);
        __half2 h1 = __floats2half2_rn(acc[1].x, acc[1].y);
        u.x = *(uint32_t*)&h0; u.y = *(uint32_t*)&h1;
        *(uint2*)o = u;
    } else {
        uint4 u;
        __half2 h0 = __floats2half2_rn(acc[0].x, acc[0].y);
        __half2 h1 = __floats2half2_rn(acc[1].x, acc[1].y);
        __half2 h2 = __floats2half2_rn(acc[2].x, acc[2].y);
        __half2 h3 = __floats2half2_rn(acc[3].x, acc[3].y);
        u.x = *(uint32_t*)&h0; u.y = *(uint32_t*)&h1;
        u.z = *(uint32_t*)&h2; u.w = *(uint32_t*)&h3;
        *(uint4*)o = u;
    }
}

// ---------------- fp16 tensor-core GEMM, cp.async double-buffered ----------------
// POOL=0: C(half) = relu(A@Bt^T + bias), stored.
// POOL=1: nothing stored; relu'd fp32 tile is pool-reduced by graph id into g_pool.
__device__ __forceinline__ void mma_f16(float* c, const uint32_t* a, const uint32_t* b) {
    asm volatile(
        "mma.sync.aligned.m16n8k16.row.col.f32.f16.f16.f32 "
        "{%0,%1,%2,%3}, {%4,%5,%6,%7}, {%8,%9}, {%0,%1,%2,%3};"
        : "+f"(c[0]), "+f"(c[1]), "+f"(c[2]), "+f"(c[3])
        : "r"(a[0]), "r"(a[1]), "r"(a[2]), "r"(a[3]), "r"(b[0]), "r"(b[1]));
}

__device__ __forceinline__ void cp16(uint32_t dst, const void* src, int bytes) {
    asm volatile("cp.async.cg.shared.global [%0], [%1], 16, %2;"
                 :: "r"(dst), "l"(src), "r"(bytes));
}

#define GM_LDS   40                           // half stride (80B, 16B mult)
#define A_ELEMS  (128 * GM_LDS)               // per buffer
#define B_ELEMS  (64 * GM_LDS)
#define AB_BYTES ((2 * A_ELEMS + 2 * B_ELEMS) * 2)   // 30720
#define SP_LDS   68                           // float stride, conflict-free
#define SP_BYTES (128 * SP_LDS * 4)           // 34816
#define SM_BYTES (SP_BYTES > AB_BYTES ? SP_BYTES : AB_BYTES)

template <int POOL>
__global__ void __launch_bounds__(256)
gemm_f16(const __half* __restrict__ A, const __half* __restrict__ Bt,
         const float* __restrict__ bias, __half* __restrict__ C,
         const int* __restrict__ batch, int M, int N, int K) {
    const int BM = 128, BK = 32;
    __shared__ __align__(16) char sm[SM_BYTES];
    __half* Asm = (__half*)sm;                       // [2][128][40]
    __half* Bsm = (__half*)(sm + 2 * A_ELEMS * 2);   // [2][64][40]
    float*  sP  = (float*)sm;                        // [128][68] (epilogue alias)

    int tid  = threadIdx.x;
    int wid  = tid >> 5, lane = tid & 31;
    int wm   = (wid >> 1) * 32, wn = (wid & 1) * 32;
    int brow = blockIdx.y * BM, bcol = blockIdx.x * 64;
    int g  = lane >> 2;    // 0..7
    int tg = lane & 3;     // 0..3

    int a_r = tid >> 2, a_c = (tid & 3) * 8;
    int b_n = tid >> 2, b_c = (tid & 3) * 8;

    float c[2][4][4] = {};
    int NT = K / BK;

    auto issue_tile = [&](int it, int buf) {
        int k0 = it * BK;
        #pragma unroll
        for (int it2 = 0; it2 < 2; it2++) {
            int r = a_r + it2 * 64;
            uint32_t dst = (uint32_t)__cvta_generic_to_shared(
                &Asm[buf * A_ELEMS + r * GM_LDS + a_c]);
            const __half* src = A + (size_t)(brow + r) * K + k0 + a_c;
            cp16(dst, src, (brow + r < M) ? 16 : 0);
        }
        {
            uint32_t dst = (uint32_t)__cvta_generic_to_shared(
                &Bsm[buf * B_ELEMS + b_n * GM_LDS + b_c]);
            const __half* src = Bt + (size_t)(bcol + b_n) * K + k0 + b_c;
            cp16(dst, src, 16);
        }
        asm volatile("cp.async.commit_group;");
    };

    issue_tile(0, 0);

    for (int it = 0; it < NT; it++) {
        int buf = it & 1;
        if (it + 1 < NT) {
            issue_tile(it + 1, buf ^ 1);
            asm volatile("cp.async.wait_group 1;");
        } else {
            asm volatile("cp.async.wait_group 0;");
        }
        __syncthreads();
        #pragma unroll
        for (int kk = 0; kk < BK; kk += 16) {
            uint32_t a[2][4], b[4][2];
            #pragma unroll
            for (int ma = 0; ma < 2; ma++) {
                int row = wm + ma * 16 + g;
                const __half* Ab = Asm + buf * A_ELEMS;
                a[ma][0] = *(const uint32_t*)&Ab[(row    ) * GM_LDS + kk + 2 * tg];
                a[ma][1] = *(const uint32_t*)&Ab[(row + 8) * GM_LDS + kk + 2 * tg];
                a[ma][2] = *(const uint32_t*)&Ab[(row    ) * GM_LDS + kk + 2 * tg + 8];
                a[ma][3] = *(const uint32_t*)&Ab[(row + 8) * GM_LDS + kk + 2 * tg + 8];
            }
            #pragma unroll
            for (int na = 0; na < 4; na++) {
                int col = wn + na * 8 + g;
                const __half* Bb = Bsm + buf * B_ELEMS;
                b[na][0] = *(const uint32_t*)&Bb[col * GM_LDS + kk + 2 * tg];
                b[na][1] = *(const uint32_t*)&Bb[col * GM_LDS + kk + 2 * tg + 8];
            }
            #pragma unroll
            for (int ma = 0; ma < 2; ma++)
                #pragma unroll
                for (int na = 0; na < 4; na++)
                    mma_f16(c[ma][na], a[ma], b[na]);
        }
        __syncthreads();
    }

    if constexpr (POOL == 0) {
        #pragma unroll
        for (int ma = 0; ma < 2; ma++) {
            int row0 = brow + wm + ma * 16 + g;
            #pragma unroll
            for (int na = 0; na < 4; na++) {
                int col = bcol + wn + na * 8 + tg * 2;
                float2 bv = *(const float2*)(bias + col);
                float v0 = fmaxf(c[ma][na][0] + bv.x, 0.f);
                float v1 = fmaxf(c[ma][na][1] + bv.y, 0.f);
                float v2 = fmaxf(c[ma][na][2] + bv.x, 0.f);
                float v3 = fmaxf(c[ma][na][3] + bv.y, 0.f);
                __half2 h0 = __floats2half2_rn(v0, v1);
                __half2 h1 = __floats2half2_rn(v2, v3);
                if (row0 < M)     *(uint32_t*)(C + (size_t)row0 * N + col)       = *(uint32_t*)&h0;
                if (row0 + 8 < M) *(uint32_t*)(C + (size_t)(row0 + 8) * N + col) = *(uint32_t*)&h1;
            }
        }
    } else {
        #pragma unroll
        for (int ma = 0; ma < 2; ma++) {
            int rl = wm + ma * 16 + g;
            #pragma unroll
            for (int na = 0; na < 4; na++) {
                int cl = wn + na * 8 + tg * 2;
                float2 bv = *(const float2*)(bias + bcol + cl);
                sP[(rl    ) * SP_LDS + cl    ] = fmaxf(c[ma][na][0] + bv.x, 0.f);
                sP[(rl    ) * SP_LDS + cl + 1] = fmaxf(c[ma][na][1] + bv.y, 0.f);
                sP[(rl + 8) * SP_LDS + cl    ] = fmaxf(c[ma][na][2] + bv.x, 0.f);
                sP[(rl + 8) * SP_LDS + cl + 1] = fmaxf(c[ma][na][3] + bv.y, 0.f);
            }
        }
        __syncthreads();
        int col = tid & 63;
        int seg = tid >> 6;
        int r0 = seg * 32, r1 = r0 + 32;
        float acc = 0.f;
        int cur = -1;
        for (int r = r0; r < r1; r++) {
            int grow = brow + r;
            if (grow >= M) break;
            int gb = batch[grow];
            if (gb != cur) {
                if (cur >= 0) atomicAdd(&g_pool[cur * HID_C + bcol + col], acc);
                cur = gb; acc = 0.f;
            }
            acc += sP[r * SP_LDS + col];
        }
        if (cur >= 0) atomicAdd(&g_pool[cur * HID_C + bcol + col], acc);
    }
}

// ---------------- fp32 SGEMM for final FC, with per-row mean folding ----------------
__global__ void __launch_bounds__(256)
sgemm_bias_mean(const float* __restrict__ A, const float* __restrict__ B,
                const float* __restrict__ bias, float* __restrict__ C,
                int M, int N, int K) {
    const int BM = 64, BN = 64, BK = 16;
    __shared__ float As[BK][BM];
    __shared__ float Bs[BK][BN];
    int tid = threadIdx.x;
    int brow = blockIdx.y * BM, bcol = blockIdx.x * BN;
    int tr = tid / 16, tc = tid % 16;
    float acc[4][4] = {};
    int ar = tid >> 2, ac = (tid & 3) * 4;
    int br = tid >> 4, bc = (tid & 15) * 4;
    float rscale = 0.f;
    if (brow + ar < M) rscale = 1.0f / fmaxf((float)g_cnt[brow + ar], 1.0f);
    for (int k0 = 0; k0 < K; k0 += BK) {
        float4 av = make_float4(0.f, 0.f, 0.f, 0.f);
        if (brow + ar < M)
            av = *(const float4*)(A + (size_t)(brow + ar) * K + k0 + ac);
        As[ac + 0][ar] = av.x * rscale; As[ac + 1][ar] = av.y * rscale;
        As[ac + 2][ar] = av.z * rscale; As[ac + 3][ar] = av.w * rscale;
        *(float4*)&Bs[br][bc] = *(const float4*)(B + (size_t)(k0 + br) * N + bcol + bc);
        __syncthreads();
        #pragma unroll
        for (int kk = 0; kk < BK; kk++) {
            float a[4], b[4];
            #pragma unroll
            for (int i = 0; i < 4; i++) a[i] = As[kk][tr * 4 + i];
            #pragma unroll
            for (int j = 0; j < 4; j++) b[j] = Bs[kk][tc * 4 + j];
            #pragma unroll
            for (int i = 0; i < 4; i++)
                #pragma unroll
                for (int j = 0; j < 4; j++)
                    acc[i][j] += a[i] * b[j];
        }
        __syncthreads();
    }
    int colb = bcol + tc * 4;
    #pragma unroll
    for (int i = 0; i < 4; i++) {
        int row = brow + tr * 4 + i;
        if (row < M) {
            float4 v;
            v.x = acc[i][0] + bias[colb + 0];
            v.y = acc[i][1] + bias[colb + 1];
            v.z = acc[i][2] + bias[colb + 2];
            v.w = acc[i][3] + bias[colb + 3];
            *(float4*)(C + (size_t)row * N + colb) = v;
        }
    }
}

// ---------------- launch ----------------
extern "C" void kernel_launch(void* const* d_in, const int* in_sizes, int n_in,
                              void* d_out, int out_size) {
    const float* x    = (const float*)d_in[0];
    const int*   ei   = (const int*)d_in[1];
    const int*   bat  = (const int*)d_in[2];
    const float* W1   = (const float*)d_in[3];
    const float* b1   = (const float*)d_in[4];
    const float* W2   = (const float*)d_in[5];
    const float* b2   = (const float*)d_in[6];
    const float* Wfc  = (const float*)d_in[7];
    const float* bfc  = (const float*)d_in[8];
    float* out = (float*)d_out;
    const int* src = ei;
    const int* dst = ei + N_EDGES;

    void *p_xh, *p_w1t, *p_w2t, *p_aggx, *p_h1, *p_aggh, *p_pool;
    cudaGetSymbolAddress(&p_xh,   g_xh);
    cudaGetSymbolAddress(&p_w1t,  g_w1t);
    cudaGetSymbolAddress(&p_w2t,  g_w2t);
    cudaGetSymbolAddress(&p_aggx, g_aggx);
    cudaGetSymbolAddress(&p_h1,   g_h1);
    cudaGetSymbolAddress(&p_aggh, g_aggh);
    cudaGetSymbolAddress(&p_pool, g_pool);

    const int T = 256;
    int nb_warps = (N_NODES * 32 + T - 1) / T; // 6250
    int nb_cvt   = (CVT_R0 + CVT_R1 + CVT_R2 + T - 1) / T;

    cvt_all_kernel<<<nb_cvt, T>>>((const float4*)x, W1, W2);  // also zeroes state
    csr_build_kernel<<<NB_SCAN, T>>>(src, dst, bat);          // hist+scan+bin fused

    // layer 1: aggregate 128 feats (S(XW) == (SX)W), then fp16 GEMM
    agg_h_kernel<IN_C><<<nb_warps, T>>>((const __half*)p_xh, (__half*)p_aggx);
    gemm_f16<0><<<dim3(HID_C / 64, (N_NODES + 127) / 128), 256>>>(
        (const __half*)p_aggx, (const __half*)p_w1t, b1, (__half*)p_h1,
        nullptr, N_NODES, HID_C, IN_C);

    // layer 2: agg, then GEMM with pooling fused into epilogue
    agg_h_kernel<HID_C><<<nb_warps, T>>>((const __half*)p_h1, (__half*)p_aggh);
    gemm_f16<1><<<dim3(HID_C / 64, (N_NODES + 127) / 128), 256>>>(
        (const __half*)p_aggh, (const __half*)p_w2t, b2, nullptr,
        bat, N_NODES, HID_C, HID_C);

    // FC on pooled sums (mean folded into A-load)
    sgemm_bias_mean<<<dim3(OUT_C / 64, (N_GRAPHS + 63) / 64), T>>>(
        (const float*)p_pool, Wfc, bfc, out, N_GRAPHS, OUT_C, HID_C);
}

// round 14
// speedup vs baseline: 1.0478x; 1.0478x over previous
#include <cuda_runtime.h>
#include <cuda_fp16.h>
#include <cstdint>
#include <cstddef>

#define N_NODES  50000
#define N_EDGES  800000
#define N_GRAPHS 128
#define IN_C     128
#define HID_C    256
#define OUT_C    128
#define NB_SCAN  ((N_NODES + 255) / 256)   // 196

// ---------------- scratch (static device globals; no allocs) ----------------
__device__ int    g_indeg[N_NODES];
__device__ int    g_cursor[N_NODES];
__device__ int    g_offsets[N_NODES + 1];
__device__ int    g_bsum[256];
__device__ int    g_csr_src[N_EDGES];
__device__ float  g_dinv[N_NODES];
__device__ __half g_xh  [(size_t)N_NODES * IN_C];
__device__ __half g_w1t [IN_C * HID_C];     // [N][K] = [256][128]
__device__ __half g_w2t [HID_C * HID_C];    // [256][256]
__device__ __half g_aggx[(size_t)N_NODES * IN_C];
__device__ __half g_h1  [(size_t)N_NODES * HID_C];
__device__ __half g_aggh[(size_t)N_NODES * HID_C];
__device__ float  g_pool[N_GRAPHS * HID_C];
__device__ int    g_cnt [N_GRAPHS];

// ---------------- setup ----------------
__global__ void hist_kernel(const int* __restrict__ dst, const int* __restrict__ batch) {
    int e = blockIdx.x * blockDim.x + threadIdx.x;
    if (e < N_EDGES) atomicAdd(&g_indeg[dst[e]], 1);
    if (e < N_NODES) atomicAdd(&g_cnt[batch[e]], 1);
}

__device__ __forceinline__ int warp_incl_scan(int v, int lane) {
    #pragma unroll
    for (int off = 1; off < 32; off <<= 1) {
        int t = __shfl_up_sync(0xffffffffu, v, off);
        if (lane >= off) v += t;
    }
    return v;
}

__global__ void __launch_bounds__(256) scan1_kernel() {
    __shared__ int wsum[8];
    int t = threadIdx.x, lane = t & 31, wid = t >> 5;
    int i = blockIdx.x * 256 + t;
    int v = (i < N_NODES) ? g_indeg[i] : 0;
    if (i < N_NODES) g_dinv[i] = rsqrtf((float)(v + 1));  // +1 self loop
    int incl = warp_incl_scan(v, lane);
    if (lane == 31) wsum[wid] = incl;
    __syncthreads();
    if (wid == 0) {
        int s = (lane < 8) ? wsum[lane] : 0;
        s = warp_incl_scan(s, lane);
        if (lane < 8) wsum[lane] = s;
    }
    __syncthreads();
    int base = (wid > 0) ? wsum[wid - 1] : 0;
    incl += base;
    if (i < N_NODES) g_offsets[i + 1] = incl;
    if (t == 255) g_bsum[blockIdx.x] = incl;
}

__global__ void __launch_bounds__(256) scan23_kernel() {
    __shared__ int wsum[8];
    __shared__ int s_base;
    int t = threadIdx.x, lane = t & 31, wid = t >> 5;
    int v = (t < NB_SCAN && t < blockIdx.x) ? g_bsum[t] : 0;
    #pragma unroll
    for (int off = 16; off > 0; off >>= 1)
        v += __shfl_down_sync(0xffffffffu, v, off);
    if (lane == 0) wsum[wid] = v;
    __syncthreads();
    if (t == 0) {
        int s = 0;
        #pragma unroll
        for (int j = 0; j < 8; j++) s += wsum[j];
        s_base = s;
    }
    __syncthreads();
    int i = blockIdx.x * 256 + t;
    if (i < N_NODES) g_offsets[i + 1] += s_base;
    if (i == 0) g_offsets[0] = 0;
}

__global__ void bin_kernel(const int* __restrict__ src, const int* __restrict__ dst) {
    int e = blockIdx.x * blockDim.x + threadIdx.x;
    if (e < N_EDGES) {
        int d = dst[e];
        int p = atomicAdd(&g_cursor[d], 1);
        g_csr_src[g_offsets[d] + p] = src[e];
    }
}

// ---- fused converts + zeroing: x->half, W1t, W2t, zero indeg/cursor/cnt/pool ----
#define CVT_R0 (N_NODES * IN_C / 4)          // 1,600,000
#define CVT_R1 (IN_C * HID_C)                // 32768
#define CVT_R2 (HID_C * HID_C)               // 65536
__global__ void __launch_bounds__(256)
cvt_all_kernel(const float4* __restrict__ x,
               const float* __restrict__ W1, const float* __restrict__ W2) {
    int i = blockIdx.x * blockDim.x + threadIdx.x;
    if (i < N_NODES) { g_indeg[i] = 0; g_cursor[i] = 0; }
    if (i < N_GRAPHS) g_cnt[i] = 0;
    if (i < N_GRAPHS * HID_C) g_pool[i] = 0.0f;

    if (i < CVT_R0) {
        float4 v = x[i];
        uint2 u;
        __half2 lo = __floats2half2_rn(v.x, v.y);
        __half2 hi = __floats2half2_rn(v.z, v.w);
        u.x = *(uint32_t*)&lo; u.y = *(uint32_t*)&hi;
        ((uint2*)g_xh)[i] = u;
        return;
    }
    int j = i - CVT_R0;
    if (j < CVT_R1) {   // W1 [K=128][N=256] -> W1t [N][K]
        int k = j / HID_C, n = j % HID_C;
        g_w1t[n * IN_C + k] = __float2half(W1[j]);
        return;
    }
    int m = j - CVT_R1;
    if (m < CVT_R2) {   // W2 [256][256] -> W2t
        int k = m / HID_C, n = m % HID_C;
        g_w2t[n * HID_C + k] = __float2half(W2[m]);
    }
}

// ---------------- aggregation: one warp per node, fp16 gather, fp32 acc ----------------
template <int F>
__device__ __forceinline__ void ld_row(const __half* __restrict__ X, int node, int lane,
                                       __half2 (&v)[F / 64]) {
    constexpr int C = F / 64;
    const __half2* xs = (const __half2*)(X + (size_t)node * F) + lane * C;
    if constexpr (C == 2) {
        uint2 u = *(const uint2*)xs;
        v[0] = *(__half2*)&u.x; v[1] = *(__half2*)&u.y;
    } else {
        uint4 u = *(const uint4*)xs;
        v[0] = *(__half2*)&u.x; v[1] = *(__half2*)&u.y;
        v[2] = *(__half2*)&u.z; v[3] = *(__half2*)&u.w;
    }
}

template <int F>
__global__ void __launch_bounds__(256)
agg_h_kernel(const __half* __restrict__ X, __half* __restrict__ O) {
    int warp = (blockIdx.x * blockDim.x + threadIdx.x) >> 5;
    int lane = threadIdx.x & 31;
    if (warp >= N_NODES) return;
    constexpr int C = F / 64;   // half2 per lane (2 or 4)
    float di = g_dinv[warp];
    float wself = di * di;

    float2 acc[C];
    {
        __half2 v[C];
        ld_row<F>(X, warp, lane, v);
        #pragma unroll
        for (int j = 0; j < C; j++) {
            float2 f = __half22float2(v[j]);
            acc[j].x = wself * f.x; acc[j].y = wself * f.y;
        }
    }
    int e0 = g_offsets[warp];
    int e1 = g_offsets[warp + 1];
    int e  = e0;
    for (; e + 1 < e1; e += 2) {
        int s0 = g_csr_src[e], s1 = g_csr_src[e + 1];
        float w0 = g_dinv[s0] * di, w1 = g_dinv[s1] * di;
        __half2 v0[C], v1[C];
        ld_row<F>(X, s0, lane, v0);
        ld_row<F>(X, s1, lane, v1);
        #pragma unroll
        for (int j = 0; j < C; j++) {
            float2 f0 = __half22float2(v0[j]);
            float2 f1 = __half22float2(v1[j]);
            acc[j].x += w0 * f0.x + w1 * f1.x;
            acc[j].y += w0 * f0.y + w1 * f1.y;
        }
    }
    if (e < e1) {
        int s = g_csr_src[e];
        float w = g_dinv[s] * di;
        __half2 v[C];
        ld_row<F>(X, s, lane, v);
        #pragma unroll
        for (int j = 0; j < C; j++) {
            float2 f = __half22float2(v[j]);
            acc[j].x += w * f.x; acc[j].y += w * f.y;
        }
    }
    __half2* o = (__half2*)(O + (size_t)warp * F) + lane * C;
    if constexpr (C == 2) {
        uint2 u;
        __half2 h0 = __floats2half2_rn(acc[0].x, acc[0].y);
        __half2 h1 = __floats2half2_rn(acc[1].x, acc[1].y);
        u.x = *(uint32_t*)&h0; u.y = *(uint32_t*)&h1;
        *(uint2*)o = u;
    } else {
        uint4 u;
        __half2 h0 = __floats2half2_rn(acc[0].x, acc[0].y);
        __half2 h1 = __floats2half2_rn(acc[1].x, acc[1].y);
        __half2 h2 = __floats2half2_rn(acc[2].x, acc[2].y);
        __half2 h3 = __floats2half2_rn(acc[3].x, acc[3].y);
        u.x = *(uint32_t*)&h0; u.y = *(uint32_t*)&h1;
        u.z = *(uint32_t*)&h2; u.w = *(uint32_t*)&h3;
        *(uint4*)o = u;
    }
}

// ---------------- fp16 tensor-core GEMM: cp.async + ldmatrix ----------------
__device__ __forceinline__ void mma_f16(float* c, const uint32_t* a, const uint32_t* b) {
    asm volatile(
        "mma.sync.aligned.m16n8k16.row.col.f32.f16.f16.f32 "
        "{%0,%1,%2,%3}, {%4,%5,%6,%7}, {%8,%9}, {%0,%1,%2,%3};"
        : "+f"(c[0]), "+f"(c[1]), "+f"(c[2]), "+f"(c[3])
        : "r"(a[0]), "r"(a[1]), "r"(a[2]), "r"(a[3]), "r"(b[0]), "r"(b[1]));
}

__device__ __forceinline__ void ldsm_x4(uint32_t& r0, uint32_t& r1,
                                        uint32_t& r2, uint32_t& r3, uint32_t addr) {
    asm volatile("ldmatrix.sync.aligned.m8n8.x4.shared.b16 {%0,%1,%2,%3}, [%4];"
                 : "=r"(r0), "=r"(r1), "=r"(r2), "=r"(r3) : "r"(addr));
}

__device__ __forceinline__ void cp16(uint32_t dst, const void* src, int bytes) {
    asm volatile("cp.async.cg.shared.global [%0], [%1], 16, %2;"
                 :: "r"(dst), "l"(src), "r"(bytes));
}

#define GM_LDS   40                           // half stride (80B; 20 words -> LDSM conflict-free)
#define A_ELEMS  (128 * GM_LDS)               // per buffer
#define B_ELEMS  (64 * GM_LDS)
#define AB_BYTES ((2 * A_ELEMS + 2 * B_ELEMS) * 2)   // 30720
#define SP_LDS   68                           // float stride, conflict-free
#define SP_BYTES (128 * SP_LDS * 4)           // 34816
#define SM_BYTES (SP_BYTES > AB_BYTES ? SP_BYTES : AB_BYTES)

// POOL=0: C(half) = relu(A@Bt^T + bias). POOL=1: fused mean-pool (sums) into g_pool.
template <int POOL>
__global__ void __launch_bounds__(256)
gemm_f16(const __half* __restrict__ A, const __half* __restrict__ Bt,
         const float* __restrict__ bias, __half* __restrict__ C,
         const int* __restrict__ batch, int M, int N, int K) {
    const int BM = 128, BK = 32;
    __shared__ __align__(16) char sm[SM_BYTES];
    __half* Asm = (__half*)sm;                       // [2][128][40]
    __half* Bsm = (__half*)(sm + 2 * A_ELEMS * 2);   // [2][64][40]
    float*  sP  = (float*)sm;                        // [128][68] (epilogue alias)

    int tid  = threadIdx.x;
    int wid  = tid >> 5, lane = tid & 31;
    int wm   = (wid >> 1) * 32, wn = (wid & 1) * 32;
    int brow = blockIdx.y * BM, bcol = blockIdx.x * 64;
    int g  = lane >> 2;    // 0..7
    int tg = lane & 3;     // 0..3

    int a_r = tid >> 2, a_c = (tid & 3) * 8;
    int b_n = tid >> 2, b_c = (tid & 3) * 8;

    // ldmatrix lane decomposition: tile index (0..3) and row within tile (0..7)
    int lt = lane >> 3, lr = lane & 7;
    // A: tile t -> rows (t&1)*8, k-half (t>>1)*8 ; B: tile t -> na (t>>1), k-half (t&1)*8
    int a_lrow = wm + (lt & 1) * 8 + lr;          // + ma*16
    int a_lcol = (lt >> 1) * 8;                   // + kk
    int b_lrow = wn + (lt >> 1) * 8 + lr;         // + np*16
    int b_lcol = (lt & 1) * 8;                    // + kk

    uint32_t As_sh = (uint32_t)__cvta_generic_to_shared(Asm);
    uint32_t Bs_sh = (uint32_t)__cvta_generic_to_shared(Bsm);

    float c[2][4][4] = {};
    int NT = K / BK;

    auto issue_tile = [&](int it, int buf) {
        int k0 = it * BK;
        #pragma unroll
        for (int it2 = 0; it2 < 2; it2++) {
            int r = a_r + it2 * 64;
            uint32_t dst = (uint32_t)__cvta_generic_to_shared(
                &Asm[buf * A_ELEMS + r * GM_LDS + a_c]);
            const __half* src = A + (size_t)(brow + r) * K + k0 + a_c;
            cp16(dst, src, (brow + r < M) ? 16 : 0);
        }
        {
            uint32_t dst = (uint32_t)__cvta_generic_to_shared(
                &Bsm[buf * B_ELEMS + b_n * GM_LDS + b_c]);
            const __half* src = Bt + (size_t)(bcol + b_n) * K + k0 + b_c;
            cp16(dst, src, 16);
        }
        asm volatile("cp.async.commit_group;");
    };

    issue_tile(0, 0);

    for (int it = 0; it < NT; it++) {
        int buf = it & 1;
        if (it + 1 < NT) {
            issue_tile(it + 1, buf ^ 1);
            asm volatile("cp.async.wait_group 1;");
        } else {
            asm volatile("cp.async.wait_group 0;");
        }
        __syncthreads();
        uint32_t Ab = As_sh + buf * (A_ELEMS * 2);
        uint32_t Bb = Bs_sh + buf * (B_ELEMS * 2);
        #pragma unroll
        for (int kk = 0; kk < BK; kk += 16) {
            uint32_t a[2][4], b[4][2];
            #pragma unroll
            for (int ma = 0; ma < 2; ma++) {
                uint32_t addr = Ab + (((a_lrow + ma * 16) * GM_LDS) + kk + a_lcol) * 2;
                ldsm_x4(a[ma][0], a[ma][1], a[ma][2], a[ma][3], addr);
            }
            #pragma unroll
            for (int np = 0; np < 2; np++) {
                uint32_t addr = Bb + (((b_lrow + np * 16) * GM_LDS) + kk + b_lcol) * 2;
                ldsm_x4(b[np * 2][0], b[np * 2][1], b[np * 2 + 1][0], b[np * 2 + 1][1], addr);
            }
            #pragma unroll
            for (int ma = 0; ma < 2; ma++)
                #pragma unroll
                for (int na = 0; na < 4; na++)
                    mma_f16(c[ma][na], a[ma], b[na]);
        }
        __syncthreads();
    }

    if constexpr (POOL == 0) {
        #pragma unroll
        for (int ma = 0; ma < 2; ma++) {
            int row0 = brow + wm + ma * 16 + g;
            #pragma unroll
            for (int na = 0; na < 4; na++) {
                int col = bcol + wn + na * 8 + tg * 2;
                float2 bv = *(const float2*)(bias + col);
                float v0 = fmaxf(c[ma][na][0] + bv.x, 0.f);
                float v1 = fmaxf(c[ma][na][1] + bv.y, 0.f);
                float v2 = fmaxf(c[ma][na][2] + bv.x, 0.f);
                float v3 = fmaxf(c[ma][na][3] + bv.y, 0.f);
                __half2 h0 = __floats2half2_rn(v0, v1);
                __half2 h1 = __floats2half2_rn(v2, v3);
                if (row0 < M)     *(uint32_t*)(C + (size_t)row0 * N + col)       = *(uint32_t*)&h0;
                if (row0 + 8 < M) *(uint32_t*)(C + (size_t)(row0 + 8) * N + col) = *(uint32_t*)&h1;
            }
        }
    } else {
        #pragma unroll
        for (int ma = 0; ma < 2; ma++) {
            int rl = wm + ma * 16 + g;
            #pragma unroll
            for (int na = 0; na < 4; na++) {
                int cl = wn + na * 8 + tg * 2;
                float2 bv = *(const float2*)(bias + bcol + cl);
                sP[(rl    ) * SP_LDS + cl    ] = fmaxf(c[ma][na][0] + bv.x, 0.f);
                sP[(rl    ) * SP_LDS + cl + 1] = fmaxf(c[ma][na][1] + bv.y, 0.f);
                sP[(rl + 8) * SP_LDS + cl    ] = fmaxf(c[ma][na][2] + bv.x, 0.f);
                sP[(rl + 8) * SP_LDS + cl + 1] = fmaxf(c[ma][na][3] + bv.y, 0.f);
            }
        }
        __syncthreads();
        int col = tid & 63;
        int seg = tid >> 6;
        int r0 = seg * 32, r1 = r0 + 32;
        float acc = 0.f;
        int cur = -1;
        for (int r = r0; r < r1; r++) {
            int grow = brow + r;
            if (grow >= M) break;
            int gb = batch[grow];
            if (gb != cur) {
                if (cur >= 0) atomicAdd(&g_pool[cur * HID_C + bcol + col], acc);
                cur = gb; acc = 0.f;
            }
            acc += sP[r * SP_LDS + col];
        }
        if (cur >= 0) atomicAdd(&g_pool[cur * HID_C + bcol + col], acc);
    }
}

// ---------------- fp32 SGEMM for final FC, with per-row mean folding ----------------
__global__ void __launch_bounds__(256)
sgemm_bias_mean(const float* __restrict__ A, const float* __restrict__ B,
                const float* __restrict__ bias, float* __restrict__ C,
                int M, int N, int K) {
    const int BM = 64, BN = 64, BK = 16;
    __shared__ float As[BK][BM];
    __shared__ float Bs[BK][BN];
    int tid = threadIdx.x;
    int brow = blockIdx.y * BM, bcol = blockIdx.x * BN;
    int tr = tid / 16, tc = tid % 16;
    float acc[4][4] = {};
    int ar = tid >> 2, ac = (tid & 3) * 4;
    int br = tid >> 4, bc = (tid & 15) * 4;
    float rscale = 0.f;
    if (brow + ar < M) rscale = 1.0f / fmaxf((float)g_cnt[brow + ar], 1.0f);
    for (int k0 = 0; k0 < K; k0 += BK) {
        float4 av = make_float4(0.f, 0.f, 0.f, 0.f);
        if (brow + ar < M)
            av = *(const float4*)(A + (size_t)(brow + ar) * K + k0 + ac);
        As[ac + 0][ar] = av.x * rscale; As[ac + 1][ar] = av.y * rscale;
        As[ac + 2][ar] = av.z * rscale; As[ac + 3][ar] = av.w * rscale;
        *(float4*)&Bs[br][bc] = *(const float4*)(B + (size_t)(k0 + br) * N + bcol + bc);
        __syncthreads();
        #pragma unroll
        for (int kk = 0; kk < BK; kk++) {
            float a[4], b[4];
            #pragma unroll
            for (int i = 0; i < 4; i++) a[i] = As[kk][tr * 4 + i];
            #pragma unroll
            for (int j = 0; j < 4; j++) b[j] = Bs[kk][tc * 4 + j];
            #pragma unroll
            for (int i = 0; i < 4; i++)
                #pragma unroll
                for (int j = 0; j < 4; j++)
                    acc[i][j] += a[i] * b[j];
        }
        __syncthreads();
    }
    int colb = bcol + tc * 4;
    #pragma unroll
    for (int i = 0; i < 4; i++) {
        int row = brow + tr * 4 + i;
        if (row < M) {
            float4 v;
            v.x = acc[i][0] + bias[colb + 0];
            v.y = acc[i][1] + bias[colb + 1];
            v.z = acc[i][2] + bias[colb + 2];
            v.w = acc[i][3] + bias[colb + 3];
            *(float4*)(C + (size_t)row * N + colb) = v;
        }
    }
}

// ---------------- launch ----------------
extern "C" void kernel_launch(void* const* d_in, const int* in_sizes, int n_in,
                              void* d_out, int out_size) {
    const float* x    = (const float*)d_in[0];
    const int*   ei   = (const int*)d_in[1];
    const int*   bat  = (const int*)d_in[2];
    const float* W1   = (const float*)d_in[3];
    const float* b1   = (const float*)d_in[4];
    const float* W2   = (const float*)d_in[5];
    const float* b2   = (const float*)d_in[6];
    const float* Wfc  = (const float*)d_in[7];
    const float* bfc  = (const float*)d_in[8];
    float* out = (float*)d_out;
    const int* src = ei;
    const int* dst = ei + N_EDGES;

    void *p_xh, *p_w1t, *p_w2t, *p_aggx, *p_h1, *p_aggh, *p_pool;
    cudaGetSymbolAddress(&p_xh,   g_xh);
    cudaGetSymbolAddress(&p_w1t,  g_w1t);
    cudaGetSymbolAddress(&p_w2t,  g_w2t);
    cudaGetSymbolAddress(&p_aggx, g_aggx);
    cudaGetSymbolAddress(&p_h1,   g_h1);
    cudaGetSymbolAddress(&p_aggh, g_aggh);
    cudaGetSymbolAddress(&p_pool, g_pool);

    const int T = 256;
    int nb_edges = (N_EDGES + T - 1) / T;      // 3125
    int nb_warps = (N_NODES * 32 + T - 1) / T; // 6250
    int nb_cvt   = (CVT_R0 + CVT_R1 + CVT_R2 + T - 1) / T;

    cvt_all_kernel<<<nb_cvt, T>>>((const float4*)x, W1, W2);  // also zeroes state
    hist_kernel<<<nb_edges, T>>>(dst, bat);
    scan1_kernel<<<NB_SCAN, T>>>();
    scan23_kernel<<<NB_SCAN, T>>>();
    bin_kernel<<<nb_edges, T>>>(src, dst);

    // layer 1: aggregate 128 feats (S(XW) == (SX)W), then fp16 GEMM
    agg_h_kernel<IN_C><<<nb_warps, T>>>((const __half*)p_xh, (__half*)p_aggx);
    gemm_f16<0><<<dim3(HID_C / 64, (N_NODES + 127) / 128), 256>>>(
        (const __half*)p_aggx, (const __half*)p_w1t, b1, (__half*)p_h1,
        nullptr, N_NODES, HID_C, IN_C);

    // layer 2: agg, then GEMM with pooling fused into epilogue
    agg_h_kernel<HID_C><<<nb_warps, T>>>((const __half*)p_h1, (__half*)p_aggh);
    gemm_f16<1><<<dim3(HID_C / 64, (N_NODES + 127) / 128), 256>>>(
        (const __half*)p_aggh, (const __half*)p_w2t, b2, nullptr,
        bat, N_NODES, HID_C, HID_C);

    // FC on pooled sums (mean folded into A-load)
    sgemm_bias_mean<<<dim3(OUT_C / 64, (N_GRAPHS + 63) / 64), T>>>(
        (const float*)p_pool, Wfc, bfc, out, N_GRAPHS, OUT_C, HID_C);
}